// round 1
// baseline (speedup 1.0000x reference)
#include <cuda_runtime.h>
#include <math.h>

#define Bsz 2
#define Lsz 2048
#define Vsz 32000
#define Esz 512
#define Hsz 1024
#define Msz 256
#define Psz 4096
#define BL  (Bsz*Lsz)      // 4096 token positions

// ---------------- scratch (static device globals; no allocation) ----------------
// float scratch layout (offsets in floats):
//  xp     [4096,3072]   @ 0          (12,582,912)
//  states [4096,1024]   @ 12,582,912 ( 4,194,304)
//  head   [4096,2048]   @ 16,777,216 ( 8,388,608)
//  bfeat  [4096, 512]   @ 25,165,824 ( 2,097,152)
//  q      [4096, 256]   @ 27,262,976 ( 1,048,576)
//  k      [4096, 256]   @ 28,311,552 ( 1,048,576)
//  gate   [4096]        @ 29,360,128 (     4,096)
//  scores [2,2048,2048] @ 29,364,224 ( 8,388,608)
//  part   [4096,4096]   @ 37,752,832 (16,777,216)
#define XP_OFF   0ul
#define ST_OFF   12582912ul
#define HEAD_OFF 16777216ul
#define BF_OFF   25165824ul
#define Q_OFF    27262976ul
#define K_OFF    28311552ul
#define GATE_OFF 29360128ul
#define SC_OFF   29364224ul
#define PART_OFF 37752832ul
#define BUF_FLOATS 54530048ul

__device__ float g_buf[BUF_FLOATS];
__device__ float g_hbuf[2][2*Hsz];   // double-buffered GRU hidden state
__device__ int   g_t2p[Vsz];
__device__ int   g_bar;

// ---------------- init kernels ----------------
__global__ void init_kernel() {
    int i = blockIdx.x*blockDim.x + threadIdx.x;
    if (i == 0) g_bar = 0;
    if (i < Vsz) g_t2p[i] = -1;
}
__global__ void t2p_kernel(const int* __restrict__ untied) {
    int p = blockIdx.x*blockDim.x + threadIdx.x;
    if (p < Psz) g_t2p[untied[p]] = p;
}

// ---------------- generic fp32 NT SGEMM ----------------
// C[M,N] = A[M,K] * B[N,K]^T (+bias[N]) ; optional row-gather on A;
// epi=1: relu(x)^2 ; beta=1: C += result.  All dims multiples of tile.
__global__ __launch_bounds__(256)
void sgemm_nt(const float* __restrict__ A, const float* __restrict__ B,
              float* __restrict__ C, const float* __restrict__ bias,
              const int* __restrict__ gatherA,
              int N, int K, int epi, int beta)
{
    __shared__ float As[16][128];
    __shared__ float Bs[16][128];
    const int tid = threadIdx.x;
    const int bm = blockIdx.y, bn = blockIdx.x;
    const int ar = tid >> 2;          // 0..63
    const int ac = (tid & 3) << 2;    // 0,4,8,12
    const int tx = tid & 15, ty = tid >> 4;

    long r0 = (long)bm*128 + ar;
    long r1 = r0 + 64;
    const float* A0 = A + (size_t)(gatherA ? (long)gatherA[r0] : r0) * K;
    const float* A1 = A + (size_t)(gatherA ? (long)gatherA[r1] : r1) * K;
    const float* B0 = B + ((size_t)bn*128 + ar) * K;
    const float* B1 = B0 + (size_t)64 * K;

    float acc[8][8];
    #pragma unroll
    for (int i=0;i<8;i++)
        #pragma unroll
        for (int j=0;j<8;j++) acc[i][j]=0.f;

    for (int k0 = 0; k0 < K; k0 += 16) {
        float4 a0 = *(const float4*)(A0 + k0 + ac);
        float4 a1 = *(const float4*)(A1 + k0 + ac);
        float4 b0 = *(const float4*)(B0 + k0 + ac);
        float4 b1 = *(const float4*)(B1 + k0 + ac);
        __syncthreads();
        As[ac+0][ar]=a0.x; As[ac+1][ar]=a0.y; As[ac+2][ar]=a0.z; As[ac+3][ar]=a0.w;
        As[ac+0][ar+64]=a1.x; As[ac+1][ar+64]=a1.y; As[ac+2][ar+64]=a1.z; As[ac+3][ar+64]=a1.w;
        Bs[ac+0][ar]=b0.x; Bs[ac+1][ar]=b0.y; Bs[ac+2][ar]=b0.z; Bs[ac+3][ar]=b0.w;
        Bs[ac+0][ar+64]=b1.x; Bs[ac+1][ar+64]=b1.y; Bs[ac+2][ar+64]=b1.z; Bs[ac+3][ar+64]=b1.w;
        __syncthreads();
        #pragma unroll
        for (int kk=0; kk<16; ++kk) {
            float a[8], b[8];
            *(float4*)&a[0] = *(const float4*)&As[kk][ty*8];
            *(float4*)&a[4] = *(const float4*)&As[kk][ty*8+4];
            *(float4*)&b[0] = *(const float4*)&Bs[kk][tx*8];
            *(float4*)&b[4] = *(const float4*)&Bs[kk][tx*8+4];
            #pragma unroll
            for (int i=0;i<8;i++)
                #pragma unroll
                for (int j=0;j<8;j++)
                    acc[i][j] = fmaf(a[i], b[j], acc[i][j]);
        }
    }

    #pragma unroll
    for (int i=0;i<8;i++) {
        size_t row = (size_t)bm*128 + ty*8 + i;
        float* crow = C + row * (size_t)N + (size_t)bn*128 + tx*8;
        #pragma unroll
        for (int j=0;j<8;j++) {
            float v = acc[i][j];
            if (bias) v += bias[bn*128 + tx*8 + j];
            if (epi == 1) { float r = fmaxf(v, 0.f); v = r*r; }
            if (beta) v += crow[j];
            crow[j] = v;
        }
    }
}

// ---------------- GRU persistent kernel (64 CTAs, grid barrier per step) ----------------
// CTA c owns h outputs j0..j0+15 (j0 = 16c); keeps w_hh rows {j, H+j, 2H+j} in smem (fp32).
#define GRU_NC 64
#define GRU_T  512
#define GRU_SMEM_FLOATS (48*Hsz + 2*Hsz + 96 + 48)

__global__ __launch_bounds__(GRU_T)
void gru_kernel(const float* __restrict__ whh, const float* __restrict__ bhh,
                const float* __restrict__ xp, float* __restrict__ states)
{
    extern __shared__ float sm[];
    float* Ws = sm;                  // [48][1024] local rows: l = g*16+jl  (g=0:r,1:z,2:n)
    float* hs = Ws + 48*Hsz;         // [2][1024] current hidden
    float* hp = hs + 2*Hsz;          // [96] dot results, idx = l*2 + b
    float* bs = hp + 96;             // [48] b_hh slice
    const int cta = blockIdx.x, tid = threadIdx.x;
    const int j0 = cta * 16;

    for (int l = 0; l < 48; ++l) {
        const float* src = whh + ((size_t)((l>>4)*Hsz + j0 + (l & 15))) * Hsz;
        for (int k = tid; k < Hsz; k += GRU_T) Ws[l*Hsz + k] = src[k];
    }
    if (tid < 48) bs[tid] = bhh[(tid>>4)*Hsz + j0 + (tid & 15)];
    for (int i = tid; i < 2*Hsz; i += GRU_T) hs[i] = 0.f;
    __syncthreads();

    const int warp = tid >> 5, lane = tid & 31;
    for (int t = 0; t < Lsz; ++t) {
        // 96 dot products (48 rows x 2 batches), 6 per warp
        #pragma unroll
        for (int i = 0; i < 6; ++i) {
            int d = warp + 16*i;
            int l = d >> 1, b = d & 1;
            const float4* w4 = (const float4*)(Ws + l*Hsz);
            const float4* h4 = (const float4*)(hs + b*Hsz);
            float s = 0.f;
            #pragma unroll 4
            for (int k = lane; k < Hsz/4; k += 32) {
                float4 w = w4[k], h = h4[k];
                s += w.x*h.x + w.y*h.y + w.z*h.z + w.w*h.w;
            }
            #pragma unroll
            for (int o = 16; o; o >>= 1) s += __shfl_down_sync(0xffffffffu, s, o);
            if (lane == 0) hp[d] = s + bs[l];
        }
        __syncthreads();
        if (tid < 32) {
            int jl = tid >> 1, b = tid & 1;
            int j = j0 + jl;
            const float* xrow = xp + ((size_t)(b*Lsz + t))*(3*Hsz);
            float hr = hp[(( 0+jl)<<1) + b];
            float hz = hp[((16+jl)<<1) + b];
            float hn = hp[((32+jl)<<1) + b];
            float xr = xrow[j], xz = xrow[Hsz + j], xn = xrow[2*Hsz + j];
            float r = 1.f/(1.f + expf(-(xr + hr)));
            float z = 1.f/(1.f + expf(-(xz + hz)));
            float n = tanhf(xn + r*hn);
            float hnew = (1.f - z)*n + z*hs[b*Hsz + j];
            states[((size_t)(b*Lsz + t))*Hsz + j] = hnew;
            g_hbuf[(t+1)&1][b*Hsz + j] = hnew;
        }
        __syncthreads();
        if (tid == 0) {
            __threadfence();
            atomicAdd(&g_bar, 1);
            int target = GRU_NC*(t+1);
            int v;
            do {
                asm volatile("ld.acquire.gpu.b32 %0, [%1];" : "=r"(v) : "l"(&g_bar));
            } while (v < target);
        }
        __syncthreads();
        const float* hb = g_hbuf[(t+1)&1];
        for (int i = tid; i < 2*Hsz; i += GRU_T) hs[i] = hb[i];
        __syncthreads();
    }
}

// ---------------- gate matvec: sigmoid(states . wg + bg) ----------------
__global__ void gate_kernel(const float* __restrict__ states, const float* __restrict__ wg,
                            const float* __restrict__ bg, float* __restrict__ gate)
{
    __shared__ float red[4];
    int row = blockIdx.x, tid = threadIdx.x;   // 128 threads
    const float* s = states + (size_t)row * Hsz;
    float acc = 0.f;
    for (int k = tid; k < Hsz; k += 128) acc += s[k]*wg[k];
    #pragma unroll
    for (int o=16;o;o>>=1) acc += __shfl_down_sync(0xffffffffu, acc, o);
    if ((tid&31)==0) red[tid>>5] = acc;
    __syncthreads();
    if (tid == 0) {
        float v = red[0]+red[1]+red[2]+red[3] + bg[0];
        gate[row] = 1.f/(1.f+expf(-v));
    }
}

// ---------------- softmax + gated scatter into mem_partial rows ----------------
__global__ __launch_bounds__(256)
void attn_kernel(const float* __restrict__ scores, const float* __restrict__ gate,
                 const int* __restrict__ input_ids, const float* __restrict__ mscale,
                 float* __restrict__ partial)
{
    __shared__ float srow[Lsz];
    __shared__ float acc[Psz];
    __shared__ float red[8];
    int qi = blockIdx.x, b = blockIdx.y, tid = threadIdx.x;
    for (int p = tid; p < Psz; p += 256) acc[p] = 0.f;
    int nk = qi;                 // strict causal: keys 0..qi-1
    if (nk > 0) {
        const float* sr = scores + ((size_t)b*Lsz + qi)*Lsz;
        float m = -3.4e38f;
        for (int k = tid; k < nk; k += 256) { float v = sr[k]*0.0625f; srow[k]=v; m = fmaxf(m, v); }
        #pragma unroll
        for (int o=16;o;o>>=1) m = fmaxf(m, __shfl_xor_sync(0xffffffffu, m, o));
        if ((tid&31)==0) red[tid>>5] = m;
        __syncthreads();
        if (tid < 32) {
            float v = (tid<8) ? red[tid] : -3.4e38f;
            #pragma unroll
            for (int o=4;o;o>>=1) v = fmaxf(v, __shfl_xor_sync(0xffffffffu, v, o));
            if (tid==0) red[0] = v;
        }
        __syncthreads();
        m = red[0];
        __syncthreads();   // all threads read red[0] before reuse
        float dsum = 0.f;
        for (int k = tid; k < nk; k += 256) { float e = expf(srow[k]-m); srow[k]=e; dsum += e; }
        #pragma unroll
        for (int o=16;o;o>>=1) dsum += __shfl_xor_sync(0xffffffffu, dsum, o);
        if ((tid&31)==0) red[tid>>5] = dsum;
        __syncthreads();
        if (tid < 32) {
            float v = (tid<8) ? red[tid] : 0.f;
            #pragma unroll
            for (int o=4;o;o>>=1) v += __shfl_xor_sync(0xffffffffu, v, o);
            if (tid==0) red[0] = v;
        }
        __syncthreads();
        float denom = red[0];                 // >= 1 (max element contributes exp(0))
        float coef = gate[b*Lsz + qi] * mscale[0] / denom;
        const int* ids = input_ids + b*Lsz;
        for (int k = tid; k < nk; k += 256) {
            int slot = g_t2p[ids[k]];
            if (slot >= 0) atomicAdd(&acc[slot], srow[k]*coef);
        }
    }
    __syncthreads();
    float* orow = partial + ((size_t)b*Lsz + qi)*Psz;
    for (int p = tid; p < Psz; p += 256) orow[p] = acc[p];
}

// ---------------- scatter total_partial into logits at untied columns ----------------
__global__ void scatter_out(const float* __restrict__ partial, const int* __restrict__ untied,
                            float* __restrict__ out)
{
    int row = blockIdx.x;
    const float* pr = partial + (size_t)row * Psz;
    float* orow = out + (size_t)row * Vsz;
    for (int p = threadIdx.x; p < Psz; p += 256) orow[untied[p]] += pr[p];
}

// ---------------- launch ----------------
extern "C" void kernel_launch(void* const* d_in, const int* in_sizes, int n_in,
                              void* d_out, int out_size)
{
    const int*   input_ids = (const int*)d_in[0];
    const int*   untied    = (const int*)d_in[1];
    const float* emb       = (const float*)d_in[2];
    const float* w_ih      = (const float*)d_in[3];
    const float* w_hh      = (const float*)d_in[4];
    const float* b_ih      = (const float*)d_in[5];
    const float* b_hh      = (const float*)d_in[6];
    const float* wq        = (const float*)d_in[7];
    const float* bq        = (const float*)d_in[8];
    const float* wk        = (const float*)d_in[9];
    const float* bk        = (const float*)d_in[10];
    const float* wg        = (const float*)d_in[11];
    const float* bg        = (const float*)d_in[12];
    const float* w_fc      = (const float*)d_in[13];
    const float* b_fc      = (const float*)d_in[14];
    const float* w_proj    = (const float*)d_in[15];
    const float* b_proj    = (const float*)d_in[16];
    const float* out_bias  = (const float*)d_in[17];
    const float* w_part    = (const float*)d_in[18];
    const float* b_part    = (const float*)d_in[19];
    const float* mscale    = (const float*)d_in[20];
    float* out = (float*)d_out;

    float* buf = nullptr;
    cudaGetSymbolAddress((void**)&buf, g_buf);
    float* xp    = buf + XP_OFF;
    float* st    = buf + ST_OFF;
    float* head  = buf + HEAD_OFF;
    float* bfeat = buf + BF_OFF;
    float* q     = buf + Q_OFF;
    float* kmat  = buf + K_OFF;
    float* gate  = buf + GATE_OFF;
    float* sc    = buf + SC_OFF;
    float* part  = buf + PART_OFF;

    cudaFuncSetAttribute(gru_kernel, cudaFuncAttributeMaxDynamicSharedMemorySize,
                         GRU_SMEM_FLOATS * (int)sizeof(float));

    // t2p table + barrier reset
    init_kernel<<<(Vsz+255)/256, 256>>>();
    t2p_kernel<<<(Psz+255)/256, 256>>>(untied);

    // xp = emb[input_ids] @ w_ih^T + b_ih          [4096,3072]
    sgemm_nt<<<dim3(3*Hsz/128, BL/128), 256>>>(emb, w_ih, xp, b_ih, input_ids, 3*Hsz, Esz, 0, 0);

    // sequential GRU -> states [4096,1024]
    gru_kernel<<<GRU_NC, GRU_T, GRU_SMEM_FLOATS*(int)sizeof(float)>>>(w_hh, b_hh, xp, st);

    // head = relu(states @ w_fc^T + b_fc)^2        [4096,2048]
    sgemm_nt<<<dim3(4*Esz/128, BL/128), 256>>>(st, w_fc, head, b_fc, nullptr, 4*Esz, Hsz, 1, 0);
    // base_feat = head @ w_proj^T + b_proj         [4096,512]
    sgemm_nt<<<dim3(Esz/128, BL/128), 256>>>(head, w_proj, bfeat, b_proj, nullptr, Esz, 4*Esz, 0, 0);
    // q, k                                          [4096,256] each
    sgemm_nt<<<dim3(Msz/128, BL/128), 256>>>(st, wq, q,    bq, nullptr, Msz, Hsz, 0, 0);
    sgemm_nt<<<dim3(Msz/128, BL/128), 256>>>(st, wk, kmat, bk, nullptr, Msz, Hsz, 0, 0);
    // gate
    gate_kernel<<<BL, 128>>>(st, wg, bg, gate);
    // scores per batch: q @ k^T                     [2048,2048]
    for (int b = 0; b < Bsz; ++b)
        sgemm_nt<<<dim3(Lsz/128, Lsz/128), 256>>>(q + (size_t)b*Lsz*Msz, kmat + (size_t)b*Lsz*Msz,
                                                  sc + (size_t)b*Lsz*Lsz, nullptr, nullptr,
                                                  Lsz, Msz, 0, 0);
    // softmax + gated scatter -> part rows
    attn_kernel<<<dim3(Lsz, Bsz), 256>>>(sc, gate, input_ids, mscale, part);
    // part += base_feat @ w_partial^T + b_partial  [4096,4096]
    sgemm_nt<<<dim3(Psz/128, BL/128), 256>>>(bfeat, w_part, part, b_part, nullptr, Psz, Esz, 0, 1);
    // logits -> out                                 [4096,32000]
    sgemm_nt<<<dim3(Vsz/128, BL/128), 256>>>(bfeat, emb, out, out_bias, nullptr, Vsz, Esz, 0, 0);
    // out[:, untied] += part
    scatter_out<<<BL, 256>>>(part, untied, out);
}

// round 3
// speedup vs baseline: 1.1853x; 1.1853x over previous
#include <cuda_runtime.h>
#include <math.h>

#define Bsz 2
#define Lsz 2048
#define Vsz 32000
#define Esz 512
#define Hsz 1024
#define Msz 256
#define Psz 4096
#define BL  (Bsz*Lsz)      // 4096 token positions

// ---------------- scratch (static device globals; no allocation) ----------------
#define XP_OFF   0ul
#define ST_OFF   12582912ul
#define HEAD_OFF 16777216ul
#define BF_OFF   25165824ul
#define Q_OFF    27262976ul
#define K_OFF    28311552ul
#define GATE_OFF 29360128ul
#define SC_OFF   29364224ul
#define PART_OFF 37752832ul
#define BUF_FLOATS 54530048ul

__device__ float g_buf[BUF_FLOATS];
__device__ float g_hbuf[2][2*Hsz];   // double-buffered GRU hidden state
__device__ int   g_t2p[Vsz];
__device__ int   g_bar;

// ---------------- init kernels ----------------
__global__ void init_kernel() {
    int i = blockIdx.x*blockDim.x + threadIdx.x;
    if (i == 0) g_bar = 0;
    if (i < Vsz) g_t2p[i] = -1;
}
__global__ void t2p_kernel(const int* __restrict__ untied) {
    int p = blockIdx.x*blockDim.x + threadIdx.x;
    if (p < Psz) g_t2p[untied[p]] = p;
}

// ---------------- TF32 tensor-core NT GEMM ----------------
// C[M,N] = A[M,K] * B[N,K]^T (+bias[N]); optional row-gather on A;
// epi=1: relu(x)^2 ; beta=1: C += result; causal=1: skip blocks with bn>bm.
// All dims multiples of 128 (N) / 16 (K). Tiles: 128x128x16, 256 thr, 8 warps,
// each warp = 64x32 via 4x4 m16n8k8 tf32 mma. smem [k][m] stride 136 (bank-clean).

__device__ __forceinline__ unsigned f2tf(float f) {
    unsigned o;
    asm("cvt.rna.tf32.f32 %0, %1;" : "=r"(o) : "f"(f));
    return o;
}
__device__ __forceinline__ void mma_tf32(float* c, const unsigned* a, const unsigned* b) {
    asm volatile(
        "mma.sync.aligned.m16n8k8.row.col.f32.tf32.tf32.f32 "
        "{%0,%1,%2,%3}, {%4,%5,%6,%7}, {%8,%9}, {%0,%1,%2,%3};"
        : "+f"(c[0]), "+f"(c[1]), "+f"(c[2]), "+f"(c[3])
        : "r"(a[0]), "r"(a[1]), "r"(a[2]), "r"(a[3]), "r"(b[0]), "r"(b[1]));
}

#define SMS 136   // smem row stride (mod 32 == 8 -> conflict-free frag loads)

__global__ __launch_bounds__(256)
void gemm_tc(const float* __restrict__ A, const float* __restrict__ B,
             float* __restrict__ C, const float* __restrict__ bias,
             const int* __restrict__ gatherA,
             int N, int K, int epi, int beta, int causal)
{
    __shared__ float As[16*SMS];
    __shared__ float Bs[16*SMS];
    const int tid = threadIdx.x;
    const int bm = blockIdx.y, bn = blockIdx.x;
    if (causal && bn > bm) return;

    // global load indices
    const int ar = tid >> 2;          // 0..63
    const int ac = (tid & 3) << 2;    // 0,4,8,12
    long r0 = (long)bm*128 + ar;
    long r1 = r0 + 64;
    const float* A0 = A + (size_t)(gatherA ? (long)gatherA[r0] : r0) * K + ac;
    const float* A1 = A + (size_t)(gatherA ? (long)gatherA[r1] : r1) * K + ac;
    const float* B0 = B + ((size_t)bn*128 + ar) * K + ac;
    const float* B1 = B0 + (size_t)64 * K;

    // warp tiling
    const int warp = tid >> 5, lane = tid & 31;
    const int wm = (warp >> 2) * 64;      // 0,64
    const int wn = (warp & 3) * 32;       // 0,32,64,96
    const int g  = lane >> 2, tg = lane & 3;

    float acc[4][4][4];
    #pragma unroll
    for (int i=0;i<4;i++)
        #pragma unroll
        for (int j=0;j<4;j++)
            #pragma unroll
            for (int r=0;r<4;r++) acc[i][j][r]=0.f;

    float4 pa0 = *(const float4*)(A0);
    float4 pa1 = *(const float4*)(A1);
    float4 pb0 = *(const float4*)(B0);
    float4 pb1 = *(const float4*)(B1);

    for (int k0 = 0; k0 < K; k0 += 16) {
        __syncthreads();
        // transpose-store prefetched data as tf32 bits
        As[(ac+0)*SMS+ar]    = __uint_as_float(f2tf(pa0.x));
        As[(ac+1)*SMS+ar]    = __uint_as_float(f2tf(pa0.y));
        As[(ac+2)*SMS+ar]    = __uint_as_float(f2tf(pa0.z));
        As[(ac+3)*SMS+ar]    = __uint_as_float(f2tf(pa0.w));
        As[(ac+0)*SMS+ar+64] = __uint_as_float(f2tf(pa1.x));
        As[(ac+1)*SMS+ar+64] = __uint_as_float(f2tf(pa1.y));
        As[(ac+2)*SMS+ar+64] = __uint_as_float(f2tf(pa1.z));
        As[(ac+3)*SMS+ar+64] = __uint_as_float(f2tf(pa1.w));
        Bs[(ac+0)*SMS+ar]    = __uint_as_float(f2tf(pb0.x));
        Bs[(ac+1)*SMS+ar]    = __uint_as_float(f2tf(pb0.y));
        Bs[(ac+2)*SMS+ar]    = __uint_as_float(f2tf(pb0.z));
        Bs[(ac+3)*SMS+ar]    = __uint_as_float(f2tf(pb0.w));
        Bs[(ac+0)*SMS+ar+64] = __uint_as_float(f2tf(pb1.x));
        Bs[(ac+1)*SMS+ar+64] = __uint_as_float(f2tf(pb1.y));
        Bs[(ac+2)*SMS+ar+64] = __uint_as_float(f2tf(pb1.z));
        Bs[(ac+3)*SMS+ar+64] = __uint_as_float(f2tf(pb1.w));
        __syncthreads();

        if (k0 + 16 < K) {   // prefetch next tile (overlaps with mma below)
            pa0 = *(const float4*)(A0 + k0 + 16);
            pa1 = *(const float4*)(A1 + k0 + 16);
            pb0 = *(const float4*)(B0 + k0 + 16);
            pb1 = *(const float4*)(B1 + k0 + 16);
        }

        #pragma unroll
        for (int ks = 0; ks < 16; ks += 8) {
            unsigned af[4][4], bf[4][2];
            const float* abase = As + (ks+tg)*SMS + wm + g;
            const float* abase4 = abase + 4*SMS;
            #pragma unroll
            for (int i=0;i<4;i++) {
                af[i][0] = __float_as_uint(abase [16*i]);
                af[i][1] = __float_as_uint(abase [16*i+8]);
                af[i][2] = __float_as_uint(abase4[16*i]);
                af[i][3] = __float_as_uint(abase4[16*i+8]);
            }
            const float* bbase = Bs + (ks+tg)*SMS + wn + g;
            const float* bbase4 = bbase + 4*SMS;
            #pragma unroll
            for (int j=0;j<4;j++) {
                bf[j][0] = __float_as_uint(bbase [8*j]);
                bf[j][1] = __float_as_uint(bbase4[8*j]);
            }
            #pragma unroll
            for (int i=0;i<4;i++)
                #pragma unroll
                for (int j=0;j<4;j++)
                    mma_tf32(acc[i][j], af[i], bf[j]);
        }
    }

    // epilogue
    #pragma unroll
    for (int i=0;i<4;i++) {
        size_t row0 = (size_t)bm*128 + wm + 16*i + g;
        size_t row1 = row0 + 8;
        #pragma unroll
        for (int j=0;j<4;j++) {
            int col = bn*128 + wn + 8*j + 2*tg;
            float b0 = 0.f, b1 = 0.f;
            if (bias) { b0 = bias[col]; b1 = bias[col+1]; }
            float v0 = acc[i][j][0] + b0, v1 = acc[i][j][1] + b1;
            float v2 = acc[i][j][2] + b0, v3 = acc[i][j][3] + b1;
            if (epi == 1) {
                float r;
                r = fmaxf(v0,0.f); v0 = r*r;
                r = fmaxf(v1,0.f); v1 = r*r;
                r = fmaxf(v2,0.f); v2 = r*r;
                r = fmaxf(v3,0.f); v3 = r*r;
            }
            float* c0 = C + row0*(size_t)N + col;
            float* c1 = C + row1*(size_t)N + col;
            if (beta) { v0 += c0[0]; v1 += c0[1]; v2 += c1[0]; v3 += c1[1]; }
            c0[0] = v0; c0[1] = v1;
            c1[0] = v2; c1[1] = v3;
        }
    }
}

// ---------------- GRU persistent kernel (64 CTAs, grid barrier per step) ----------------
#define GRU_NC 64
#define GRU_T  512
#define GRU_SMEM_FLOATS (48*Hsz + 2*Hsz + 96 + 48)

__global__ __launch_bounds__(GRU_T)
void gru_kernel(const float* __restrict__ whh, const float* __restrict__ bhh,
                const float* __restrict__ xp, float* __restrict__ states)
{
    extern __shared__ float sm[];
    float* Ws = sm;                  // [48][1024] rows: l = g*16+jl  (g=0:r,1:z,2:n)
    float* hs = Ws + 48*Hsz;         // [2][1024] current hidden
    float* hp = hs + 2*Hsz;          // [96] dot results, idx = l*2 + b
    float* bs = hp + 96;             // [48] b_hh slice
    const int cta = blockIdx.x, tid = threadIdx.x;
    const int j0 = cta * 16;

    for (int l = 0; l < 48; ++l) {
        const float* src = whh + ((size_t)((l>>4)*Hsz + j0 + (l & 15))) * Hsz;
        for (int k = tid; k < Hsz; k += GRU_T) Ws[l*Hsz + k] = src[k];
    }
    if (tid < 48) bs[tid] = bhh[(tid>>4)*Hsz + j0 + (tid & 15)];
    for (int i = tid; i < 2*Hsz; i += GRU_T) hs[i] = 0.f;
    __syncthreads();

    const int warp = tid >> 5, lane = tid & 31;
    for (int t = 0; t < Lsz; ++t) {
        #pragma unroll
        for (int i = 0; i < 6; ++i) {
            int d = warp + 16*i;
            int l = d >> 1, b = d & 1;
            const float4* w4 = (const float4*)(Ws + l*Hsz);
            const float4* h4 = (const float4*)(hs + b*Hsz);
            float s = 0.f;
            #pragma unroll 4
            for (int k = lane; k < Hsz/4; k += 32) {
                float4 w = w4[k], h = h4[k];
                s += w.x*h.x + w.y*h.y + w.z*h.z + w.w*h.w;
            }
            #pragma unroll
            for (int o = 16; o; o >>= 1) s += __shfl_down_sync(0xffffffffu, s, o);
            if (lane == 0) hp[d] = s + bs[l];
        }
        __syncthreads();
        if (tid < 32) {
            int jl = tid >> 1, b = tid & 1;
            int j = j0 + jl;
            const float* xrow = xp + ((size_t)(b*Lsz + t))*(3*Hsz);
            float hr = hp[(( 0+jl)<<1) + b];
            float hz = hp[((16+jl)<<1) + b];
            float hn = hp[((32+jl)<<1) + b];
            float xr = xrow[j], xz = xrow[Hsz + j], xn = xrow[2*Hsz + j];
            float r = 1.f/(1.f + expf(-(xr + hr)));
            float z = 1.f/(1.f + expf(-(xz + hz)));
            float n = tanhf(xn + r*hn);
            float hnew = (1.f - z)*n + z*hs[b*Hsz + j];
            states[((size_t)(b*Lsz + t))*Hsz + j] = hnew;
            g_hbuf[(t+1)&1][b*Hsz + j] = hnew;
        }
        __syncthreads();
        if (tid == 0) {
            __threadfence();
            atomicAdd(&g_bar, 1);
            int target = GRU_NC*(t+1);
            int v;
            do {
                asm volatile("ld.acquire.gpu.b32 %0, [%1];" : "=r"(v) : "l"(&g_bar));
            } while (v < target);
        }
        __syncthreads();
        const float* hb = g_hbuf[(t+1)&1];
        for (int i = tid; i < 2*Hsz; i += GRU_T) hs[i] = hb[i];
        __syncthreads();
    }
}

// ---------------- gate matvec: sigmoid(states . wg + bg) ----------------
__global__ void gate_kernel(const float* __restrict__ states, const float* __restrict__ wg,
                            const float* __restrict__ bg, float* __restrict__ gate)
{
    __shared__ float red[4];
    int row = blockIdx.x, tid = threadIdx.x;   // 128 threads
    const float* s = states + (size_t)row * Hsz;
    float acc = 0.f;
    for (int k = tid; k < Hsz; k += 128) acc += s[k]*wg[k];
    #pragma unroll
    for (int o=16;o;o>>=1) acc += __shfl_down_sync(0xffffffffu, acc, o);
    if ((tid&31)==0) red[tid>>5] = acc;
    __syncthreads();
    if (tid == 0) {
        float v = red[0]+red[1]+red[2]+red[3] + bg[0];
        gate[row] = 1.f/(1.f+expf(-v));
    }
}

// ---------------- softmax + gated scatter into mem_partial rows ----------------
__global__ __launch_bounds__(256)
void attn_kernel(const float* __restrict__ scores, const float* __restrict__ gate,
                 const int* __restrict__ input_ids, const float* __restrict__ mscale,
                 float* __restrict__ partial)
{
    __shared__ float srow[Lsz];
    __shared__ float acc[Psz];
    __shared__ float red[8];
    int qi = blockIdx.x, b = blockIdx.y, tid = threadIdx.x;
    for (int p = tid; p < Psz; p += 256) acc[p] = 0.f;
    int nk = qi;                 // strict causal: keys 0..qi-1
    if (nk > 0) {
        const float* sr = scores + ((size_t)b*Lsz + qi)*Lsz;
        float m = -3.4e38f;
        for (int k = tid; k < nk; k += 256) { float v = sr[k]*0.0625f; srow[k]=v; m = fmaxf(m, v); }
        #pragma unroll
        for (int o=16;o;o>>=1) m = fmaxf(m, __shfl_xor_sync(0xffffffffu, m, o));
        if ((tid&31)==0) red[tid>>5] = m;
        __syncthreads();
        if (tid < 32) {
            float v = (tid<8) ? red[tid] : -3.4e38f;
            #pragma unroll
            for (int o=4;o;o>>=1) v = fmaxf(v, __shfl_xor_sync(0xffffffffu, v, o));
            if (tid==0) red[0] = v;
        }
        __syncthreads();
        m = red[0];
        __syncthreads();
        float dsum = 0.f;
        for (int k = tid; k < nk; k += 256) { float e = expf(srow[k]-m); srow[k]=e; dsum += e; }
        #pragma unroll
        for (int o=16;o;o>>=1) dsum += __shfl_xor_sync(0xffffffffu, dsum, o);
        if ((tid&31)==0) red[tid>>5] = dsum;
        __syncthreads();
        if (tid < 32) {
            float v = (tid<8) ? red[tid] : 0.f;
            #pragma unroll
            for (int o=4;o;o>>=1) v += __shfl_xor_sync(0xffffffffu, v, o);
            if (tid==0) red[0] = v;
        }
        __syncthreads();
        float denom = red[0];
        float coef = gate[b*Lsz + qi] * mscale[0] / denom;
        const int* ids = input_ids + b*Lsz;
        for (int k = tid; k < nk; k += 256) {
            int slot = g_t2p[ids[k]];
            if (slot >= 0) atomicAdd(&acc[slot], srow[k]*coef);
        }
    }
    __syncthreads();
    float* orow = partial + ((size_t)b*Lsz + qi)*Psz;
    for (int p = tid; p < Psz; p += 256) orow[p] = acc[p];
}

// ---------------- scatter total_partial into logits at untied columns ----------------
__global__ void scatter_out(const float* __restrict__ partial, const int* __restrict__ untied,
                            float* __restrict__ out)
{
    int row = blockIdx.x;
    const float* pr = partial + (size_t)row * Psz;
    float* orow = out + (size_t)row * Vsz;
    for (int p = threadIdx.x; p < Psz; p += 256) orow[untied[p]] += pr[p];
}

// ---------------- launch ----------------
extern "C" void kernel_launch(void* const* d_in, const int* in_sizes, int n_in,
                              void* d_out, int out_size)
{
    const int*   input_ids = (const int*)d_in[0];
    const int*   untied    = (const int*)d_in[1];
    const float* emb       = (const float*)d_in[2];
    const float* w_ih      = (const float*)d_in[3];
    const float* w_hh      = (const float*)d_in[4];
    const float* b_ih      = (const float*)d_in[5];
    const float* b_hh      = (const float*)d_in[6];
    const float* wq        = (const float*)d_in[7];
    const float* bq        = (const float*)d_in[8];
    const float* wk        = (const float*)d_in[9];
    const float* bk        = (const float*)d_in[10];
    const float* wg        = (const float*)d_in[11];
    const float* bg        = (const float*)d_in[12];
    const float* w_fc      = (const float*)d_in[13];
    const float* b_fc      = (const float*)d_in[14];
    const float* w_proj    = (const float*)d_in[15];
    const float* b_proj    = (const float*)d_in[16];
    const float* out_bias  = (const float*)d_in[17];
    const float* w_part    = (const float*)d_in[18];
    const float* b_part    = (const float*)d_in[19];
    const float* mscale    = (const float*)d_in[20];
    float* out = (float*)d_out;

    float* buf = nullptr;
    cudaGetSymbolAddress((void**)&buf, g_buf);
    float* xp    = buf + XP_OFF;
    float* st    = buf + ST_OFF;
    float* head  = buf + HEAD_OFF;
    float* bfeat = buf + BF_OFF;
    float* q     = buf + Q_OFF;
    float* kmat  = buf + K_OFF;
    float* gate  = buf + GATE_OFF;
    float* sc    = buf + SC_OFF;
    float* part  = buf + PART_OFF;

    cudaFuncSetAttribute(gru_kernel, cudaFuncAttributeMaxDynamicSharedMemorySize,
                         GRU_SMEM_FLOATS * (int)sizeof(float));

    init_kernel<<<(Vsz+255)/256, 256>>>();
    t2p_kernel<<<(Psz+255)/256, 256>>>(untied);

    // xp = emb[input_ids] @ w_ih^T + b_ih          [4096,3072]
    gemm_tc<<<dim3(3*Hsz/128, BL/128), 256>>>(emb, w_ih, xp, b_ih, input_ids, 3*Hsz, Esz, 0, 0, 0);

    // sequential GRU -> states [4096,1024]
    gru_kernel<<<GRU_NC, GRU_T, GRU_SMEM_FLOATS*(int)sizeof(float)>>>(w_hh, b_hh, xp, st);

    // head = relu(states @ w_fc^T + b_fc)^2        [4096,2048]
    gemm_tc<<<dim3(4*Esz/128, BL/128), 256>>>(st, w_fc, head, b_fc, nullptr, 4*Esz, Hsz, 1, 0, 0);
    // base_feat = head @ w_proj^T + b_proj         [4096,512]
    gemm_tc<<<dim3(Esz/128, BL/128), 256>>>(head, w_proj, bfeat, b_proj, nullptr, Esz, 4*Esz, 0, 0, 0);
    // q, k                                          [4096,256] each
    gemm_tc<<<dim3(Msz/128, BL/128), 256>>>(st, wq, q,    bq, nullptr, Msz, Hsz, 0, 0, 0);
    gemm_tc<<<dim3(Msz/128, BL/128), 256>>>(st, wk, kmat, bk, nullptr, Msz, Hsz, 0, 0, 0);
    // gate
    gate_kernel<<<BL, 128>>>(st, wg, bg, gate);
    // scores per batch: q @ k^T (lower-triangular blocks only)
    for (int b = 0; b < Bsz; ++b)
        gemm_tc<<<dim3(Lsz/128, Lsz/128), 256>>>(q + (size_t)b*Lsz*Msz, kmat + (size_t)b*Lsz*Msz,
                                                 sc + (size_t)b*Lsz*Lsz, nullptr, nullptr,
                                                 Lsz, Msz, 0, 0, 1);
    // softmax + gated scatter -> part rows
    attn_kernel<<<dim3(Lsz, Bsz), 256>>>(sc, gate, input_ids, mscale, part);
    // part += base_feat @ w_partial^T + b_partial  [4096,4096]
    gemm_tc<<<dim3(Psz/128, BL/128), 256>>>(bfeat, w_part, part, b_part, nullptr, Psz, Esz, 0, 1, 0);
    // logits -> out                                 [4096,32000]
    gemm_tc<<<dim3(Vsz/128, BL/128), 256>>>(bfeat, emb, out, out_bias, nullptr, Vsz, Esz, 0, 0, 0);
    // out[:, untied] += part
    scatter_out<<<BL, 256>>>(part, untied, out);
}

// round 16
// speedup vs baseline: 2.0479x; 1.7277x over previous
#include <cuda_runtime.h>
#include <math.h>

#define Bsz 2
#define Lsz 2048
#define Vsz 32000
#define Esz 512
#define Hsz 1024
#define Msz 256
#define Psz 4096
#define BL  (Bsz*Lsz)      // 4096 token positions

// ---------------- scratch (static device globals; no allocation) ----------------
#define XP_OFF   0ul
#define ST_OFF   12582912ul
#define HEAD_OFF 16777216ul
#define BF_OFF   25165824ul
#define Q_OFF    27262976ul
#define K_OFF    28311552ul
#define GATE_OFF 29360128ul
#define SC_OFF   29364224ul
#define PART_OFF 37752832ul
#define BUF_FLOATS 54530048ul

__device__ float g_buf[BUF_FLOATS];
__device__ float g_hbuf[2][2*Hsz];   // double-buffered GRU hidden state
__device__ int   g_t2p[Vsz];
__device__ int   g_bar2[2];          // per-batch GRU grid barrier

// ---------------- init kernels ----------------
__global__ void init_kernel() {
    int i = blockIdx.x*blockDim.x + threadIdx.x;
    if (i < 2) g_bar2[i] = 0;
    if (i < Vsz) g_t2p[i] = -1;
}
__global__ void t2p_kernel(const int* __restrict__ untied) {
    int p = blockIdx.x*blockDim.x + threadIdx.x;
    if (p < Psz) g_t2p[untied[p]] = p;
}

// ---------------- TF32 tensor-core NT GEMM (double-buffered smem) ----------------
// C[M,N] = A[M,K] * B[N,K]^T (+bias[N]); optional row-gather on A;
// epi=1: relu(x)^2 ; beta=1: C += result; causal=1: skip blocks with bn>bm.

__device__ __forceinline__ unsigned f2tf(float f) {
    unsigned o;
    asm("cvt.rna.tf32.f32 %0, %1;" : "=r"(o) : "f"(f));
    return o;
}
__device__ __forceinline__ void mma_tf32(float* c, const unsigned* a, const unsigned* b) {
    asm volatile(
        "mma.sync.aligned.m16n8k8.row.col.f32.tf32.tf32.f32 "
        "{%0,%1,%2,%3}, {%4,%5,%6,%7}, {%8,%9}, {%0,%1,%2,%3};"
        : "+f"(c[0]), "+f"(c[1]), "+f"(c[2]), "+f"(c[3])
        : "r"(a[0]), "r"(a[1]), "r"(a[2]), "r"(a[3]), "r"(b[0]), "r"(b[1]));
}

#define SMS 136   // smem row stride (mod 32 == 8 -> conflict-free frag loads)

__global__ __launch_bounds__(256)
void gemm_tc(const float* __restrict__ A, const float* __restrict__ B,
             float* __restrict__ C, const float* __restrict__ bias,
             const int* __restrict__ gatherA,
             int N, int K, int epi, int beta, int causal)
{
    __shared__ float As[2][16*SMS];
    __shared__ float Bs[2][16*SMS];
    const int tid = threadIdx.x;
    const int bm = blockIdx.y, bn = blockIdx.x;
    if (causal && bn > bm) return;

    const int ar = tid >> 2;          // 0..63
    const int ac = (tid & 3) << 2;    // 0,4,8,12
    long r0 = (long)bm*128 + ar;
    long r1 = r0 + 64;
    const float* A0 = A + (size_t)(gatherA ? (long)gatherA[r0] : r0) * K + ac;
    const float* A1 = A + (size_t)(gatherA ? (long)gatherA[r1] : r1) * K + ac;
    const float* B0 = B + ((size_t)bn*128 + ar) * K + ac;
    const float* B1 = B0 + (size_t)64 * K;

    const int warp = tid >> 5, lane = tid & 31;
    const int wm = (warp >> 2) * 64;      // 0,64
    const int wn = (warp & 3) * 32;       // 0,32,64,96
    const int g  = lane >> 2, tg = lane & 3;

    float acc[4][4][4];
    #pragma unroll
    for (int i=0;i<4;i++)
        #pragma unroll
        for (int j=0;j<4;j++)
            #pragma unroll
            for (int r=0;r<4;r++) acc[i][j][r]=0.f;

    float4 pa0 = *(const float4*)(A0);
    float4 pa1 = *(const float4*)(A1);
    float4 pb0 = *(const float4*)(B0);
    float4 pb1 = *(const float4*)(B1);

    // store tile 0 into buffer 0
    {
        float* as = As[0]; float* bs_ = Bs[0];
        as[(ac+0)*SMS+ar]    = __uint_as_float(f2tf(pa0.x));
        as[(ac+1)*SMS+ar]    = __uint_as_float(f2tf(pa0.y));
        as[(ac+2)*SMS+ar]    = __uint_as_float(f2tf(pa0.z));
        as[(ac+3)*SMS+ar]    = __uint_as_float(f2tf(pa0.w));
        as[(ac+0)*SMS+ar+64] = __uint_as_float(f2tf(pa1.x));
        as[(ac+1)*SMS+ar+64] = __uint_as_float(f2tf(pa1.y));
        as[(ac+2)*SMS+ar+64] = __uint_as_float(f2tf(pa1.z));
        as[(ac+3)*SMS+ar+64] = __uint_as_float(f2tf(pa1.w));
        bs_[(ac+0)*SMS+ar]    = __uint_as_float(f2tf(pb0.x));
        bs_[(ac+1)*SMS+ar]    = __uint_as_float(f2tf(pb0.y));
        bs_[(ac+2)*SMS+ar]    = __uint_as_float(f2tf(pb0.z));
        bs_[(ac+3)*SMS+ar]    = __uint_as_float(f2tf(pb0.w));
        bs_[(ac+0)*SMS+ar+64] = __uint_as_float(f2tf(pb1.x));
        bs_[(ac+1)*SMS+ar+64] = __uint_as_float(f2tf(pb1.y));
        bs_[(ac+2)*SMS+ar+64] = __uint_as_float(f2tf(pb1.z));
        bs_[(ac+3)*SMS+ar+64] = __uint_as_float(f2tf(pb1.w));
    }
    __syncthreads();

    int cur = 0;
    for (int k0 = 0; k0 < K; k0 += 16) {
        const int more = (k0 + 16 < K);
        if (more) {   // LDGs in flight during the MMA block below
            pa0 = *(const float4*)(A0 + k0 + 16);
            pa1 = *(const float4*)(A1 + k0 + 16);
            pb0 = *(const float4*)(B0 + k0 + 16);
            pb1 = *(const float4*)(B1 + k0 + 16);
        }

        const float* asr = As[cur];
        const float* bsr = Bs[cur];
        #pragma unroll
        for (int ks = 0; ks < 16; ks += 8) {
            unsigned af[4][4], bf[4][2];
            const float* abase = asr + (ks+tg)*SMS + wm + g;
            const float* abase4 = abase + 4*SMS;
            #pragma unroll
            for (int i=0;i<4;i++) {
                af[i][0] = __float_as_uint(abase [16*i]);
                af[i][1] = __float_as_uint(abase [16*i+8]);
                af[i][2] = __float_as_uint(abase4[16*i]);
                af[i][3] = __float_as_uint(abase4[16*i+8]);
            }
            const float* bbase = bsr + (ks+tg)*SMS + wn + g;
            const float* bbase4 = bbase + 4*SMS;
            #pragma unroll
            for (int j=0;j<4;j++) {
                bf[j][0] = __float_as_uint(bbase [8*j]);
                bf[j][1] = __float_as_uint(bbase4[8*j]);
            }
            #pragma unroll
            for (int i=0;i<4;i++)
                #pragma unroll
                for (int j=0;j<4;j++)
                    mma_tf32(acc[i][j], af[i], bf[j]);
        }

        if (more) {   // store into the other buffer; one sync per tile
            float* as = As[cur^1]; float* bs_ = Bs[cur^1];
            as[(ac+0)*SMS+ar]    = __uint_as_float(f2tf(pa0.x));
            as[(ac+1)*SMS+ar]    = __uint_as_float(f2tf(pa0.y));
            as[(ac+2)*SMS+ar]    = __uint_as_float(f2tf(pa0.z));
            as[(ac+3)*SMS+ar]    = __uint_as_float(f2tf(pa0.w));
            as[(ac+0)*SMS+ar+64] = __uint_as_float(f2tf(pa1.x));
            as[(ac+1)*SMS+ar+64] = __uint_as_float(f2tf(pa1.y));
            as[(ac+2)*SMS+ar+64] = __uint_as_float(f2tf(pa1.z));
            as[(ac+3)*SMS+ar+64] = __uint_as_float(f2tf(pa1.w));
            bs_[(ac+0)*SMS+ar]    = __uint_as_float(f2tf(pb0.x));
            bs_[(ac+1)*SMS+ar]    = __uint_as_float(f2tf(pb0.y));
            bs_[(ac+2)*SMS+ar]    = __uint_as_float(f2tf(pb0.z));
            bs_[(ac+3)*SMS+ar]    = __uint_as_float(f2tf(pb0.w));
            bs_[(ac+0)*SMS+ar+64] = __uint_as_float(f2tf(pb1.x));
            bs_[(ac+1)*SMS+ar+64] = __uint_as_float(f2tf(pb1.y));
            bs_[(ac+2)*SMS+ar+64] = __uint_as_float(f2tf(pb1.z));
            bs_[(ac+3)*SMS+ar+64] = __uint_as_float(f2tf(pb1.w));
            __syncthreads();
            cur ^= 1;
        }
    }

    #pragma unroll
    for (int i=0;i<4;i++) {
        size_t row0 = (size_t)bm*128 + wm + 16*i + g;
        size_t row1 = row0 + 8;
        #pragma unroll
        for (int j=0;j<4;j++) {
            int col = bn*128 + wn + 8*j + 2*tg;
            float b0 = 0.f, b1 = 0.f;
            if (bias) { b0 = bias[col]; b1 = bias[col+1]; }
            float v0 = acc[i][j][0] + b0, v1 = acc[i][j][1] + b1;
            float v2 = acc[i][j][2] + b0, v3 = acc[i][j][3] + b1;
            if (epi == 1) {
                float r;
                r = fmaxf(v0,0.f); v0 = r*r;
                r = fmaxf(v1,0.f); v1 = r*r;
                r = fmaxf(v2,0.f); v2 = r*r;
                r = fmaxf(v3,0.f); v3 = r*r;
            }
            float* c0 = C + row0*(size_t)N + col;
            float* c1 = C + row1*(size_t)N + col;
            if (beta) { v0 += c0[0]; v1 += c0[1]; v2 += c1[0]; v3 += c1[1]; }
            c0[0] = v0; c0[1] = v1;
            c1[0] = v2; c1[1] = v3;
        }
    }
}

// ---------------- GRU persistent kernel v2 ----------------
// 128 CTAs: cta/64 = batch, cta%64 -> 16 h-outputs. 48 w_hh rows in smem (192KB).
// Per step: h cached in registers per lane (8 float4), 3 w-rows per warp streamed
// once, dual use of h -> smem traffic ~256KB/step (was 768KB). Per-batch barriers.
#define GRU_NC 128
#define GRU_T  512
#define GRU_SMEM_FLOATS (48*Hsz + Hsz + 48 + 48)

__global__ __launch_bounds__(GRU_T)
void gru_kernel(const float* __restrict__ whh, const float* __restrict__ bhh,
                const float* __restrict__ xp, float* __restrict__ states)
{
    extern __shared__ float sm[];
    float* Ws = sm;                  // [48][1024] rows: l = g*16+jl (g=0:r,1:z,2:n)
    float* hs = Ws + 48*Hsz;         // [1024] current hidden (own batch)
    float* hp = hs + Hsz;            // [48] dot results indexed by l
    float* bs = hp + 48;             // [48] b_hh slice
    const int cta = blockIdx.x, tid = threadIdx.x;
    const int b  = cta >> 6;         // batch
    const int j0 = (cta & 63) << 4;  // first of 16 owned h-outputs

    for (int l = 0; l < 48; ++l) {
        const float* src = whh + ((size_t)((l>>4)*Hsz + j0 + (l & 15))) * Hsz;
        for (int k = tid; k < Hsz; k += GRU_T) Ws[l*Hsz + k] = src[k];
    }
    if (tid < 48) bs[tid] = bhh[(tid>>4)*Hsz + j0 + (tid & 15)];
    for (int i = tid; i < Hsz; i += GRU_T) hs[i] = 0.f;
    __syncthreads();

    const int warp = tid >> 5, lane = tid & 31;
    const float4* w0 = (const float4*)(Ws + (3*warp+0)*Hsz);
    const float4* w1 = (const float4*)(Ws + (3*warp+1)*Hsz);
    const float4* w2 = (const float4*)(Ws + (3*warp+2)*Hsz);
    const float* xbase = xp + ((size_t)b*Lsz)*(3*Hsz);
    int buf = 1;

    for (int t = 0; t < Lsz; ++t) {
        // prefetch this step's gate inputs (hidden behind the matvec)
        float xr = 0.f, xz = 0.f, xn = 0.f;
        if (tid < 16) {
            const float* xrow = xbase + (size_t)t*(3*Hsz) + j0 + tid;
            xr = xrow[0]; xz = xrow[Hsz]; xn = xrow[2*Hsz];
        }
        // h cached in registers; 3 dot rows per warp sharing the h registers
        float a0 = 0.f, a1 = 0.f, a2 = 0.f;
        const float4* hv = (const float4*)hs;
        #pragma unroll
        for (int i = 0; i < 8; ++i) {
            float4 h = hv[lane + 32*i];
            float4 u = w0[lane + 32*i];
            a0 += u.x*h.x + u.y*h.y + u.z*h.z + u.w*h.w;
            float4 v = w1[lane + 32*i];
            a1 += v.x*h.x + v.y*h.y + v.z*h.z + v.w*h.w;
            float4 s = w2[lane + 32*i];
            a2 += s.x*h.x + s.y*h.y + s.z*h.z + s.w*h.w;
        }
        #pragma unroll
        for (int o = 16; o; o >>= 1) {
            a0 += __shfl_down_sync(0xffffffffu, a0, o);
            a1 += __shfl_down_sync(0xffffffffu, a1, o);
            a2 += __shfl_down_sync(0xffffffffu, a2, o);
        }
        if (lane == 0) {
            hp[3*warp+0] = a0 + bs[3*warp+0];
            hp[3*warp+1] = a1 + bs[3*warp+1];
            hp[3*warp+2] = a2 + bs[3*warp+2];
        }
        __syncthreads();
        if (tid < 16) {
            int j = j0 + tid;
            float r = 1.f/(1.f + expf(-(xr + hp[tid])));
            float z = 1.f/(1.f + expf(-(xz + hp[16+tid])));
            float n = tanhf(xn + r*hp[32+tid]);
            float hnew = (1.f - z)*n + z*hs[j];
            states[((size_t)(b*Lsz + t))*Hsz + j] = hnew;
            g_hbuf[buf][b*Hsz + j] = hnew;
        }
        __syncthreads();
        if (tid == 0) {
            __threadfence();
            atomicAdd(&g_bar2[b], 1);
            int target = 64*(t+1);
            int v;
            do {
                asm volatile("ld.acquire.gpu.b32 %0, [%1];" : "=r"(v) : "l"(&g_bar2[b]));
            } while (v < target);
        }
        __syncthreads();
        const float* hb = g_hbuf[buf] + b*Hsz;
        for (int i = tid; i < Hsz; i += GRU_T) hs[i] = hb[i];
        buf ^= 1;
        __syncthreads();
    }
}

// ---------------- gate matvec: sigmoid(states . wg + bg) ----------------
__global__ void gate_kernel(const float* __restrict__ states, const float* __restrict__ wg,
                            const float* __restrict__ bg, float* __restrict__ gate)
{
    __shared__ float red[4];
    int row = blockIdx.x, tid = threadIdx.x;   // 128 threads
    const float* s = states + (size_t)row * Hsz;
    float acc = 0.f;
    for (int k = tid; k < Hsz; k += 128) acc += s[k]*wg[k];
    #pragma unroll
    for (int o=16;o;o>>=1) acc += __shfl_down_sync(0xffffffffu, acc, o);
    if ((tid&31)==0) red[tid>>5] = acc;
    __syncthreads();
    if (tid == 0) {
        float v = red[0]+red[1]+red[2]+red[3] + bg[0];
        gate[row] = 1.f/(1.f+expf(-v));
    }
}

// ---------------- softmax + gated scatter into mem_partial rows ----------------
__global__ __launch_bounds__(256)
void attn_kernel(const float* __restrict__ scores, const float* __restrict__ gate,
                 const int* __restrict__ input_ids, const float* __restrict__ mscale,
                 float* __restrict__ partial)
{
    __shared__ float srow[Lsz];
    __shared__ float acc[Psz];
    __shared__ float red[8];
    int qi = blockIdx.x, b = blockIdx.y, tid = threadIdx.x;
    for (int p = tid; p < Psz; p += 256) acc[p] = 0.f;
    int nk = qi;                 // strict causal: keys 0..qi-1
    if (nk > 0) {
        const float* sr = scores + ((size_t)b*Lsz + qi)*Lsz;
        float m = -3.4e38f;
        for (int k = tid; k < nk; k += 256) { float v = sr[k]*0.0625f; srow[k]=v; m = fmaxf(m, v); }
        #pragma unroll
        for (int o=16;o;o>>=1) m = fmaxf(m, __shfl_xor_sync(0xffffffffu, m, o));
        if ((tid&31)==0) red[tid>>5] = m;
        __syncthreads();
        if (tid < 32) {
            float v = (tid<8) ? red[tid] : -3.4e38f;
            #pragma unroll
            for (int o=4;o;o>>=1) v = fmaxf(v, __shfl_xor_sync(0xffffffffu, v, o));
            if (tid==0) red[0] = v;
        }
        __syncthreads();
        m = red[0];
        __syncthreads();
        float dsum = 0.f;
        for (int k = tid; k < nk; k += 256) { float e = expf(srow[k]-m); srow[k]=e; dsum += e; }
        #pragma unroll
        for (int o=16;o;o>>=1) dsum += __shfl_xor_sync(0xffffffffu, dsum, o);
        if ((tid&31)==0) red[tid>>5] = dsum;
        __syncthreads();
        if (tid < 32) {
            float v = (tid<8) ? red[tid] : 0.f;
            #pragma unroll
            for (int o=4;o;o>>=1) v += __shfl_xor_sync(0xffffffffu, v, o);
            if (tid==0) red[0] = v;
        }
        __syncthreads();
        float denom = red[0];
        float coef = gate[b*Lsz + qi] * mscale[0] / denom;
        const int* ids = input_ids + b*Lsz;
        for (int k = tid; k < nk; k += 256) {
            int slot = g_t2p[ids[k]];
            if (slot >= 0) atomicAdd(&acc[slot], srow[k]*coef);
        }
    }
    __syncthreads();
    float* orow = partial + ((size_t)b*Lsz + qi)*Psz;
    for (int p = tid; p < Psz; p += 256) orow[p] = acc[p];
}

// ---------------- scatter total_partial into logits at untied columns ----------------
__global__ void scatter_out(const float* __restrict__ partial, const int* __restrict__ untied,
                            float* __restrict__ out)
{
    int row = blockIdx.x;
    const float* pr = partial + (size_t)row * Psz;
    float* orow = out + (size_t)row * Vsz;
    for (int p = threadIdx.x; p < Psz; p += 256) orow[untied[p]] += pr[p];
}

// ---------------- launch ----------------
extern "C" void kernel_launch(void* const* d_in, const int* in_sizes, int n_in,
                              void* d_out, int out_size)
{
    const int*   input_ids = (const int*)d_in[0];
    const int*   untied    = (const int*)d_in[1];
    const float* emb       = (const float*)d_in[2];
    const float* w_ih      = (const float*)d_in[3];
    const float* w_hh      = (const float*)d_in[4];
    const float* b_ih      = (const float*)d_in[5];
    const float* b_hh      = (const float*)d_in[6];
    const float* wq        = (const float*)d_in[7];
    const float* bq        = (const float*)d_in[8];
    const float* wk        = (const float*)d_in[9];
    const float* bk        = (const float*)d_in[10];
    const float* wg        = (const float*)d_in[11];
    const float* bg        = (const float*)d_in[12];
    const float* w_fc      = (const float*)d_in[13];
    const float* b_fc      = (const float*)d_in[14];
    const float* w_proj    = (const float*)d_in[15];
    const float* b_proj    = (const float*)d_in[16];
    const float* out_bias  = (const float*)d_in[17];
    const float* w_part    = (const float*)d_in[18];
    const float* b_part    = (const float*)d_in[19];
    const float* mscale    = (const float*)d_in[20];
    float* out = (float*)d_out;

    float* buf = nullptr;
    cudaGetSymbolAddress((void**)&buf, g_buf);
    float* xp    = buf + XP_OFF;
    float* st    = buf + ST_OFF;
    float* head  = buf + HEAD_OFF;
    float* bfeat = buf + BF_OFF;
    float* q     = buf + Q_OFF;
    float* kmat  = buf + K_OFF;
    float* gate  = buf + GATE_OFF;
    float* sc    = buf + SC_OFF;
    float* part  = buf + PART_OFF;

    cudaFuncSetAttribute(gru_kernel, cudaFuncAttributeMaxDynamicSharedMemorySize,
                         GRU_SMEM_FLOATS * (int)sizeof(float));

    init_kernel<<<(Vsz+255)/256, 256>>>();
    t2p_kernel<<<(Psz+255)/256, 256>>>(untied);

    // xp = emb[input_ids] @ w_ih^T + b_ih          [4096,3072]
    gemm_tc<<<dim3(3*Hsz/128, BL/128), 256>>>(emb, w_ih, xp, b_ih, input_ids, 3*Hsz, Esz, 0, 0, 0);

    // sequential GRU -> states [4096,1024]
    gru_kernel<<<GRU_NC, GRU_T, GRU_SMEM_FLOATS*(int)sizeof(float)>>>(w_hh, b_hh, xp, st);

    // head = relu(states @ w_fc^T + b_fc)^2        [4096,2048]
    gemm_tc<<<dim3(4*Esz/128, BL/128), 256>>>(st, w_fc, head, b_fc, nullptr, 4*Esz, Hsz, 1, 0, 0);
    // base_feat = head @ w_proj^T + b_proj         [4096,512]
    gemm_tc<<<dim3(Esz/128, BL/128), 256>>>(head, w_proj, bfeat, b_proj, nullptr, Esz, 4*Esz, 0, 0, 0);
    // q, k                                          [4096,256] each
    gemm_tc<<<dim3(Msz/128, BL/128), 256>>>(st, wq, q,    bq, nullptr, Msz, Hsz, 0, 0, 0);
    gemm_tc<<<dim3(Msz/128, BL/128), 256>>>(st, wk, kmat, bk, nullptr, Msz, Hsz, 0, 0, 0);
    // gate
    gate_kernel<<<BL, 128>>>(st, wg, bg, gate);
    // scores per batch: q @ k^T (lower-triangular blocks only)
    for (int b = 0; b < Bsz; ++b)
        gemm_tc<<<dim3(Lsz/128, Lsz/128), 256>>>(q + (size_t)b*Lsz*Msz, kmat + (size_t)b*Lsz*Msz,
                                                 sc + (size_t)b*Lsz*Lsz, nullptr, nullptr,
                                                 Lsz, Msz, 0, 0, 1);
    // softmax + gated scatter -> part rows
    attn_kernel<<<dim3(Lsz, Bsz), 256>>>(sc, gate, input_ids, mscale, part);
    // part += base_feat @ w_partial^T + b_partial  [4096,4096]
    gemm_tc<<<dim3(Psz/128, BL/128), 256>>>(bfeat, w_part, part, b_part, nullptr, Psz, Esz, 0, 1, 0);
    // logits -> out                                 [4096,32000]
    gemm_tc<<<dim3(Vsz/128, BL/128), 256>>>(bfeat, emb, out, out_bias, nullptr, Vsz, Esz, 0, 0, 0);
    // out[:, untied] += part
    scatter_out<<<BL, 256>>>(part, untied, out);
}